// round 15
// baseline (speedup 1.0000x reference)
#include <cuda_runtime.h>
#include <cstdint>

#define NN   50000
#define EMBD 256
#define NE   800000
#define ETOT (NE + NN)
#define NBLK 196                      // ceil(NN/256)

// ---------------- static device scratch ----------------
__device__ float g_h[(size_t)NN * EMBD];
__device__ float g_o1[(size_t)NN * EMBD];
__device__ float g_als[NN * 8];       // layer-1 (H=8) logit pieces
__device__ float g_ald[NN * 8];
__device__ float g_als2[NN];          // layer-2 (H=1)
__device__ float g_ald2[NN];
__device__ int   g_rowptr[NN + 1];
__device__ int   g_cnt[NN];
__device__ int   g_srcs[ETOT];
__device__ int   g_tmp[NN];
__device__ int   g_bsum[NBLK];
__device__ int   g_is64;

__device__ __forceinline__ float lrelu(float x) { return x > 0.f ? x : 0.2f * x; }

__device__ __forceinline__ uint32_t f2tf(float f) {
    uint32_t u;
    asm("cvt.rna.tf32.f32 %0, %1;" : "=r"(u) : "f"(f));
    return u;
}

__device__ __forceinline__ void gbar(int id) {
    asm volatile("bar.sync %0, 64;" :: "r"(id) : "memory");
}

// ---------------- init: zero counters + logit accumulators + dtype probe ----------------
__global__ void init_kernel(const void* ei) {
    const int i = blockIdx.x * blockDim.x + threadIdx.x;
    const int stride = gridDim.x * blockDim.x;
    if (i < NN) { g_cnt[i] = 0; g_als2[i] = 0.f; g_ald2[i] = 0.f; }
    for (int j = i; j < NN * 8; j += stride) { g_als[j] = 0.f; g_ald[j] = 0.f; }
    if (i == 0) {
        const long long* p = (const long long*)ei;
        bool ok = true;
        #pragma unroll
        for (int k = 0; k < 8; k++) {
            long long v = p[k];
            if (v < 0 || v >= NN) ok = false;
        }
        g_is64 = ok ? 1 : 0;
    }
}

// ---------------- CSR build (4 edges / thread) ----------------
__global__ void deg_kernel(const void* __restrict__ ei) {
    int e4 = blockIdx.x * blockDim.x + threadIdx.x;
    if (e4 >= NE / 4) return;
    if (!g_is64) {
        int4 d = ((const int4*)((const int*)ei + NE))[e4];
        atomicAdd(&g_cnt[d.x], 1);
        atomicAdd(&g_cnt[d.y], 1);
        atomicAdd(&g_cnt[d.z], 1);
        atomicAdd(&g_cnt[d.w], 1);
    } else {
        const long long* p = (const long long*)ei + NE;
        #pragma unroll
        for (int k = 0; k < 4; k++) atomicAdd(&g_cnt[(int)p[e4 * 4 + k]], 1);
    }
}

__global__ void __launch_bounds__(256) scan1_kernel() {
    __shared__ int wsum[8];
    const int t = threadIdx.x, b = blockIdx.x;
    const int i = b * 256 + t;
    int v = (i < NN) ? g_cnt[i] + 1 : 0;
    int x = v;
    #pragma unroll
    for (int o = 1; o < 32; o <<= 1) {
        int y = __shfl_up_sync(0xffffffffu, x, o);
        if ((t & 31) >= o) x += y;
    }
    if ((t & 31) == 31) wsum[t >> 5] = x;
    __syncthreads();
    if (t < 8) {
        int w = wsum[t];
        #pragma unroll
        for (int o = 1; o < 8; o <<= 1) {
            int y = __shfl_up_sync(0xffu, w, o);
            if (t >= o) w += y;
        }
        wsum[t] = w;
    }
    __syncthreads();
    int incl = x + ((t >= 32) ? wsum[(t >> 5) - 1] : 0);
    if (i < NN) g_tmp[i] = incl;
    if (t == 255) g_bsum[b] = incl;
}

// merged scan2+scan3
__global__ void __launch_bounds__(256) scan_apply_kernel() {
    __shared__ int red[8];
    __shared__ int s_off;
    const int t = threadIdx.x, b = blockIdx.x;
    int v = (t < b) ? g_bsum[t] : 0;
    #pragma unroll
    for (int o = 16; o; o >>= 1) v += __shfl_xor_sync(0xffffffffu, v, o);
    if ((t & 31) == 0) red[t >> 5] = v;
    __syncthreads();
    if (t == 0) {
        int s = 0;
        #pragma unroll
        for (int ww = 0; ww < 8; ww++) s += red[ww];
        s_off = s;
        if (b == 0) g_rowptr[0] = 0;
    }
    __syncthreads();
    const int i = b * 256 + t;
    if (i < NN) {
        int rp1 = g_tmp[i] + s_off;
        g_rowptr[i + 1] = rp1;
        g_cnt[i] = 0;
        g_srcs[rp1 - 1] = i;
    }
}

__global__ void scatter_kernel(const void* __restrict__ ei) {
    int e4 = blockIdx.x * blockDim.x + threadIdx.x;
    if (e4 >= NE / 4) return;
    int s[4], d[4];
    if (!g_is64) {
        int4 sv = ((const int4*)ei)[e4];
        int4 dv = ((const int4*)((const int*)ei + NE))[e4];
        s[0] = sv.x; s[1] = sv.y; s[2] = sv.z; s[3] = sv.w;
        d[0] = dv.x; d[1] = dv.y; d[2] = dv.z; d[3] = dv.w;
    } else {
        const long long* ps = (const long long*)ei;
        const long long* pd = ps + NE;
        #pragma unroll
        for (int k = 0; k < 4; k++) { s[k] = (int)ps[e4 * 4 + k]; d[k] = (int)pd[e4 * 4 + k]; }
    }
    #pragma unroll
    for (int k = 0; k < 4; k++) {
        int pos = g_rowptr[d[k]] + atomicAdd(&g_cnt[d[k]], 1);
        g_srcs[pos] = s[k];
    }
}

// ---------------- tf32 GEMM, 2-stage double-buffered (16-wide K chunks), fused al epilogue ----
template <int H, bool INTERNAL_SRC>
__global__ void __launch_bounds__(256) gemm_tc_kernel(const float* __restrict__ Aext,
                                                      const float* __restrict__ B,
                                                      const float* __restrict__ asrc,
                                                      const float* __restrict__ adst, int M) {
    const float* A = INTERNAL_SRC ? g_o1 : Aext;
    float* C = g_h;
    float* ALS = (H == 8) ? g_als : g_als2;
    float* ALD = (H == 8) ? g_ald : g_ald2;

    __shared__ uint32_t As[2][16][129];
    __shared__ uint32_t Bs[2][16][132];

    const int t    = threadIdx.x;
    const int lane = t & 31;
    const int w    = t >> 5;
    const int wr   = w & 3;
    const int wc   = w >> 2;
    const int tig  = lane & 3;
    const int gid  = lane >> 2;
    const int bm   = blockIdx.x * 128;
    const int bn   = blockIdx.y * 128;

    float acc[2][8][4];
    #pragma unroll
    for (int mt = 0; mt < 2; mt++)
        #pragma unroll
        for (int nt = 0; nt < 8; nt++)
            #pragma unroll
            for (int c = 0; c < 4; c++) acc[mt][nt][c] = 0.f;

    const int a_r  = t >> 2;           // 0..63
    const int a_ko = (t & 3) * 4;      // 0,4,8,12

    float4 pa[2], pb[2];

    // prefetch chunk 0
    #pragma unroll
    for (int i = 0; i < 2; i++) {
        int grow = bm + a_r + i * 64;
        pa[i] = (grow < M) ? *(const float4*)(A + (size_t)grow * EMBD + a_ko)
                           : make_float4(0.f, 0.f, 0.f, 0.f);
    }
    #pragma unroll
    for (int i = 0; i < 2; i++) {
        int idx = t + i * 256;
        int kr  = idx >> 5;            // 0..15
        int c4  = (idx & 31) * 4;
        pb[i] = *(const float4*)(B + (size_t)kr * EMBD + bn + c4);
    }

    #pragma unroll 1
    for (int kc = 0; kc < 16; kc++) {
        const int p = kc & 1;
        // stage prefetched chunk into buffer p
        #pragma unroll
        for (int i = 0; i < 2; i++) {
            int r = a_r + i * 64;
            As[p][a_ko + 0][r] = f2tf(pa[i].x);
            As[p][a_ko + 1][r] = f2tf(pa[i].y);
            As[p][a_ko + 2][r] = f2tf(pa[i].z);
            As[p][a_ko + 3][r] = f2tf(pa[i].w);
        }
        #pragma unroll
        for (int i = 0; i < 2; i++) {
            int idx = t + i * 256;
            int kr  = idx >> 5;
            int c4  = (idx & 31) * 4;
            uint4 u;
            u.x = f2tf(pb[i].x); u.y = f2tf(pb[i].y); u.z = f2tf(pb[i].z); u.w = f2tf(pb[i].w);
            *(uint4*)&Bs[p][kr][c4] = u;
        }
        __syncthreads();

        // prefetch next chunk (overlaps mma)
        if (kc + 1 < 16) {
            const int kbase = (kc + 1) * 16;
            #pragma unroll
            for (int i = 0; i < 2; i++) {
                int grow = bm + a_r + i * 64;
                pa[i] = (grow < M) ? *(const float4*)(A + (size_t)grow * EMBD + kbase + a_ko)
                                   : make_float4(0.f, 0.f, 0.f, 0.f);
            }
            #pragma unroll
            for (int i = 0; i < 2; i++) {
                int idx = t + i * 256;
                int kr  = idx >> 5;
                int c4  = (idx & 31) * 4;
                pb[i] = *(const float4*)(B + (size_t)(kbase + kr) * EMBD + bn + c4);
            }
        }

        // mma over the 16-wide chunk (2 k-steps of 8)
        #pragma unroll
        for (int k0 = 0; k0 < 16; k0 += 8) {
            uint32_t af[2][4], bf[8][2];
            const int kr0 = k0 + tig, kr1 = k0 + tig + 4;
            #pragma unroll
            for (int mt = 0; mt < 2; mt++) {
                int m0 = wr * 32 + mt * 16 + gid;
                af[mt][0] = As[p][kr0][m0];
                af[mt][1] = As[p][kr0][m0 + 8];
                af[mt][2] = As[p][kr1][m0];
                af[mt][3] = As[p][kr1][m0 + 8];
            }
            #pragma unroll
            for (int nt = 0; nt < 8; nt++) {
                int n0 = wc * 64 + nt * 8 + gid;
                bf[nt][0] = Bs[p][kr0][n0];
                bf[nt][1] = Bs[p][kr1][n0];
            }
            #pragma unroll
            for (int mt = 0; mt < 2; mt++)
                #pragma unroll
                for (int nt = 0; nt < 8; nt++) {
                    asm volatile(
                        "mma.sync.aligned.m16n8k8.row.col.f32.tf32.tf32.f32 "
                        "{%0,%1,%2,%3}, {%4,%5,%6,%7}, {%8,%9}, {%0,%1,%2,%3};\n"
                        : "+f"(acc[mt][nt][0]), "+f"(acc[mt][nt][1]),
                          "+f"(acc[mt][nt][2]), "+f"(acc[mt][nt][3])
                        : "r"(af[mt][0]), "r"(af[mt][1]), "r"(af[mt][2]), "r"(af[mt][3]),
                          "r"(bf[nt][0]), "r"(bf[nt][1]));
                }
        }
    }

    // store C
    #pragma unroll
    for (int mt = 0; mt < 2; mt++) {
        int row0 = bm + wr * 32 + mt * 16 + gid;
        #pragma unroll
        for (int nt = 0; nt < 8; nt++) {
            int col = bn + wc * 64 + nt * 8 + tig * 2;
            if (row0 < M)
                *(float2*)(C + (size_t)row0 * EMBD + col) = make_float2(acc[mt][nt][0], acc[mt][nt][1]);
            if (row0 + 8 < M)
                *(float2*)(C + (size_t)(row0 + 8) * EMBD + col) = make_float2(acc[mt][nt][2], acc[mt][nt][3]);
        }
    }

    // fused al epilogue
    float as_[16], ad_[16];
    #pragma unroll
    for (int nt = 0; nt < 8; nt++)
        #pragma unroll
        for (int c = 0; c < 2; c++) {
            int col = bn + wc * 64 + nt * 8 + tig * 2 + c;
            as_[nt * 2 + c] = __ldg(&asrc[col]);
            ad_[nt * 2 + c] = __ldg(&adst[col]);
        }

    #pragma unroll
    for (int mt = 0; mt < 2; mt++) {
        #pragma unroll
        for (int rs = 0; rs < 2; rs++) {
            float ps0 = 0.f, ps1 = 0.f, pd0 = 0.f, pd1 = 0.f;
            #pragma unroll
            for (int nt = 0; nt < 8; nt++)
                #pragma unroll
                for (int c = 0; c < 2; c++) {
                    float v = acc[mt][nt][rs * 2 + c];
                    float a = as_[nt * 2 + c], dd = ad_[nt * 2 + c];
                    if (nt < 4) { ps0 += v * a; pd0 += v * dd; }
                    else        { ps1 += v * a; pd1 += v * dd; }
                }
            if (H == 1) { ps0 += ps1; pd0 += pd1; }
            #pragma unroll
            for (int o = 1; o < 4; o <<= 1) {
                ps0 += __shfl_xor_sync(0xffffffffu, ps0, o);
                pd0 += __shfl_xor_sync(0xffffffffu, pd0, o);
                if (H == 8) {
                    ps1 += __shfl_xor_sync(0xffffffffu, ps1, o);
                    pd1 += __shfl_xor_sync(0xffffffffu, pd1, o);
                }
            }
            if (tig == 0) {
                int row = bm + wr * 32 + mt * 16 + gid + rs * 8;
                if (row < M) {
                    if (H == 8) {
                        int head0 = (bn >> 5) + wc * 2;
                        atomicAdd(&ALS[row * 8 + head0], ps0);
                        atomicAdd(&ALS[row * 8 + head0 + 1], ps1);
                        atomicAdd(&ALD[row * 8 + head0], pd0);
                        atomicAdd(&ALD[row * 8 + head0 + 1], pd1);
                    } else {
                        atomicAdd(&ALS[row], ps0);
                        atomicAdd(&ALD[row], pd0);
                    }
                }
            }
        }
    }
}

// ---------------- FUSED alpha + aggregation: 4 nodes/block, 64-thread groups ----------------
template <int H, bool INTERNAL_DST>
__global__ void __launch_bounds__(256) agg_kernel(const float* __restrict__ bias,
                                                  float* __restrict__ outext) {
    const int t  = threadIdx.x;
    const int g  = t >> 6;
    const int t4 = t & 63;
    const int c0 = t4 * 4;
    const int hh = (H == 8) ? (c0 >> 5) : 0;
    const int d  = blockIdx.x * 4 + g;   // NN % 4 == 0

    const float* ALS = (H == 8) ? g_als : g_als2;
    const float* ALD = (H == 8) ? g_ald : g_ald2;

    __shared__ int   s_src[4][64];
    __shared__ float s_alpha[4][64 * H];

    const int begin = g_rowptr[d], end = g_rowptr[d + 1];
    const float aldv = ALD[d * H + ((H == 8) ? (t4 & 7) : 0)];

    float4 acc = make_float4(0.f, 0.f, 0.f, 0.f);
    float z = 0.f;

    for (int c = begin; c < end; c += 64) {
        int len = min(64, end - c);
        gbar(1 + g);
        if (t4 < len) s_src[g][t4] = g_srcs[c + t4];
        gbar(1 + g);
        if (H == 8) {
            for (int idx = t4; idx < len * 8; idx += 64) {
                int j = idx >> 3, h = idx & 7;
                s_alpha[g][idx] = __expf(lrelu(__ldg(&ALS[s_src[g][j] * 8 + h]) + aldv));
            }
        } else {
            for (int idx = t4; idx < len; idx += 64)
                s_alpha[g][idx] = __expf(lrelu(__ldg(&ALS[s_src[g][idx]]) + aldv));
        }
        gbar(1 + g);
        for (int j = 0; j < len; j++) {
            float a = s_alpha[g][j * H + hh];
            z += a;
            const float4 hv = *(const float4*)(g_h + (size_t)s_src[g][j] * EMBD + c0);
            acc.x += a * hv.x; acc.y += a * hv.y; acc.z += a * hv.z; acc.w += a * hv.w;
        }
    }

    const float inv = 1.f / (z + 1e-16f);
    const float4 bv = *(const float4*)(bias + c0);
    float4 r = make_float4(acc.x * inv + bv.x, acc.y * inv + bv.y,
                           acc.z * inv + bv.z, acc.w * inv + bv.w);
    float* dst = INTERNAL_DST ? (g_o1 + (size_t)d * EMBD + c0)
                              : (outext + (size_t)d * EMBD + c0);
    *(float4*)dst = r;
}

// ---------------- launch ----------------
extern "C" void kernel_launch(void* const* d_in, const int* in_sizes, int n_in,
                              void* d_out, int out_size) {
    const float* x   = (const float*)d_in[0];
    const void*  ei  = d_in[1];
    const float* W1  = (const float*)d_in[2];
    const float* as1 = (const float*)d_in[3];
    const float* ad1 = (const float*)d_in[4];
    const float* b1  = (const float*)d_in[5];
    const float* W2  = (const float*)d_in[6];
    const float* as2 = (const float*)d_in[7];
    const float* ad2 = (const float*)d_in[8];
    const float* b2  = (const float*)d_in[9];
    float* out = (float*)d_out;

    init_kernel<<<(NN * 8 + 255) / 256, 256>>>(ei);
    deg_kernel<<<(NE / 4 + 255) / 256, 256>>>(ei);
    scan1_kernel<<<NBLK, 256>>>();
    scan_apply_kernel<<<NBLK, 256>>>();
    scatter_kernel<<<(NE / 4 + 255) / 256, 256>>>(ei);

    dim3 gg((NN + 127) / 128, 2);
    const int AGB = NN / 4;

    // layer 1 (H=8, F=32)
    gemm_tc_kernel<8, false><<<gg, 256>>>(x, W1, as1, ad1, NN);
    agg_kernel<8, true><<<AGB, 256>>>(b1, nullptr);

    // layer 2 (H=1, F=256)
    gemm_tc_kernel<1, true><<<gg, 256>>>(nullptr, W2, as2, ad2, NN);
    agg_kernel<1, false><<<AGB, 256>>>(b2, out);
}

// round 16
// speedup vs baseline: 1.0337x; 1.0337x over previous
#include <cuda_runtime.h>
#include <cstdint>

#define NN   50000
#define EMBD 256
#define NE   800000
#define ETOT (NE + NN)
#define NBLK 196                      // ceil(NN/256)

// ---------------- static device scratch ----------------
__device__ float g_h[(size_t)NN * EMBD];
__device__ float g_o1[(size_t)NN * EMBD];
__device__ float g_als[NN * 8];       // layer-1 (H=8) logit pieces
__device__ float g_ald[NN * 8];
__device__ float g_als2[NN];          // layer-2 (H=1)
__device__ float g_ald2[NN];
__device__ int   g_rowptr[NN + 1];
__device__ int   g_cnt[NN];
__device__ int   g_srcs[ETOT];
__device__ int   g_tmp[NN];
__device__ int   g_bsum[NBLK];
__device__ int   g_is64;

__device__ __forceinline__ float lrelu(float x) { return x > 0.f ? x : 0.2f * x; }

__device__ __forceinline__ uint32_t f2tf(float f) {
    uint32_t u;
    asm("cvt.rna.tf32.f32 %0, %1;" : "=r"(u) : "f"(f));
    return u;
}

__device__ __forceinline__ void gbar(int id) {
    asm volatile("bar.sync %0, 64;" :: "r"(id) : "memory");
}

// ---------------- init: zero counters + logit accumulators + dtype probe ----------------
__global__ void init_kernel(const void* ei) {
    const int i = blockIdx.x * blockDim.x + threadIdx.x;
    const int stride = gridDim.x * blockDim.x;
    if (i < NN) { g_cnt[i] = 0; g_als2[i] = 0.f; g_ald2[i] = 0.f; }
    for (int j = i; j < NN * 8; j += stride) { g_als[j] = 0.f; g_ald[j] = 0.f; }
    if (i == 0) {
        const long long* p = (const long long*)ei;
        bool ok = true;
        #pragma unroll
        for (int k = 0; k < 8; k++) {
            long long v = p[k];
            if (v < 0 || v >= NN) ok = false;
        }
        g_is64 = ok ? 1 : 0;
    }
}

// ---------------- CSR build (4 edges / thread) ----------------
__global__ void deg_kernel(const void* __restrict__ ei) {
    int e4 = blockIdx.x * blockDim.x + threadIdx.x;
    if (e4 >= NE / 4) return;
    if (!g_is64) {
        int4 d = ((const int4*)((const int*)ei + NE))[e4];
        atomicAdd(&g_cnt[d.x], 1);
        atomicAdd(&g_cnt[d.y], 1);
        atomicAdd(&g_cnt[d.z], 1);
        atomicAdd(&g_cnt[d.w], 1);
    } else {
        const long long* p = (const long long*)ei + NE;
        #pragma unroll
        for (int k = 0; k < 4; k++) atomicAdd(&g_cnt[(int)p[e4 * 4 + k]], 1);
    }
}

__global__ void __launch_bounds__(256) scan1_kernel() {
    __shared__ int wsum[8];
    const int t = threadIdx.x, b = blockIdx.x;
    const int i = b * 256 + t;
    int v = (i < NN) ? g_cnt[i] + 1 : 0;
    int x = v;
    #pragma unroll
    for (int o = 1; o < 32; o <<= 1) {
        int y = __shfl_up_sync(0xffffffffu, x, o);
        if ((t & 31) >= o) x += y;
    }
    if ((t & 31) == 31) wsum[t >> 5] = x;
    __syncthreads();
    if (t < 8) {
        int w = wsum[t];
        #pragma unroll
        for (int o = 1; o < 8; o <<= 1) {
            int y = __shfl_up_sync(0xffu, w, o);
            if (t >= o) w += y;
        }
        wsum[t] = w;
    }
    __syncthreads();
    int incl = x + ((t >= 32) ? wsum[(t >> 5) - 1] : 0);
    if (i < NN) g_tmp[i] = incl;
    if (t == 255) g_bsum[b] = incl;
}

// merged scan2+scan3
__global__ void __launch_bounds__(256) scan_apply_kernel() {
    __shared__ int red[8];
    __shared__ int s_off;
    const int t = threadIdx.x, b = blockIdx.x;
    int v = (t < b) ? g_bsum[t] : 0;
    #pragma unroll
    for (int o = 16; o; o >>= 1) v += __shfl_xor_sync(0xffffffffu, v, o);
    if ((t & 31) == 0) red[t >> 5] = v;
    __syncthreads();
    if (t == 0) {
        int s = 0;
        #pragma unroll
        for (int ww = 0; ww < 8; ww++) s += red[ww];
        s_off = s;
        if (b == 0) g_rowptr[0] = 0;
    }
    __syncthreads();
    const int i = b * 256 + t;
    if (i < NN) {
        int rp1 = g_tmp[i] + s_off;
        g_rowptr[i + 1] = rp1;
        g_cnt[i] = 0;
        g_srcs[rp1 - 1] = i;
    }
}

__global__ void scatter_kernel(const void* __restrict__ ei) {
    int e4 = blockIdx.x * blockDim.x + threadIdx.x;
    if (e4 >= NE / 4) return;
    int s[4], d[4];
    if (!g_is64) {
        int4 sv = ((const int4*)ei)[e4];
        int4 dv = ((const int4*)((const int*)ei + NE))[e4];
        s[0] = sv.x; s[1] = sv.y; s[2] = sv.z; s[3] = sv.w;
        d[0] = dv.x; d[1] = dv.y; d[2] = dv.z; d[3] = dv.w;
    } else {
        const long long* ps = (const long long*)ei;
        const long long* pd = ps + NE;
        #pragma unroll
        for (int k = 0; k < 4; k++) { s[k] = (int)ps[e4 * 4 + k]; d[k] = (int)pd[e4 * 4 + k]; }
    }
    #pragma unroll
    for (int k = 0; k < 4; k++) {
        int pos = g_rowptr[d[k]] + atomicAdd(&g_cnt[d[k]], 1);
        g_srcs[pos] = s[k];
    }
}

// ---------------- tf32 GEMM, 2-stage double-buffered, 2 CTAs/SM, fused al epilogue ----------
template <int H, bool INTERNAL_SRC>
__global__ void __launch_bounds__(256, 2) gemm_tc_kernel(const float* __restrict__ Aext,
                                                         const float* __restrict__ B,
                                                         const float* __restrict__ asrc,
                                                         const float* __restrict__ adst, int M) {
    const float* A = INTERNAL_SRC ? g_o1 : Aext;
    float* C = g_h;
    float* ALS = (H == 8) ? g_als : g_als2;
    float* ALD = (H == 8) ? g_ald : g_ald2;

    __shared__ uint32_t As[2][16][129];
    __shared__ uint32_t Bs[2][16][132];

    const int t    = threadIdx.x;
    const int lane = t & 31;
    const int w    = t >> 5;
    const int wr   = w & 3;
    const int wc   = w >> 2;
    const int tig  = lane & 3;
    const int gid  = lane >> 2;
    const int bm   = blockIdx.x * 128;
    const int bn   = blockIdx.y * 128;

    float acc[2][8][4];
    #pragma unroll
    for (int mt = 0; mt < 2; mt++)
        #pragma unroll
        for (int nt = 0; nt < 8; nt++)
            #pragma unroll
            for (int c = 0; c < 4; c++) acc[mt][nt][c] = 0.f;

    const int a_r  = t >> 2;           // 0..63
    const int a_ko = (t & 3) * 4;      // 0,4,8,12

    float4 pa[2], pb[2];

    // prefetch chunk 0
    #pragma unroll
    for (int i = 0; i < 2; i++) {
        int grow = bm + a_r + i * 64;
        pa[i] = (grow < M) ? *(const float4*)(A + (size_t)grow * EMBD + a_ko)
                           : make_float4(0.f, 0.f, 0.f, 0.f);
    }
    #pragma unroll
    for (int i = 0; i < 2; i++) {
        int idx = t + i * 256;
        int kr  = idx >> 5;            // 0..15
        int c4  = (idx & 31) * 4;
        pb[i] = *(const float4*)(B + (size_t)kr * EMBD + bn + c4);
    }

    #pragma unroll 1
    for (int kc = 0; kc < 16; kc++) {
        const int p = kc & 1;
        #pragma unroll
        for (int i = 0; i < 2; i++) {
            int r = a_r + i * 64;
            As[p][a_ko + 0][r] = f2tf(pa[i].x);
            As[p][a_ko + 1][r] = f2tf(pa[i].y);
            As[p][a_ko + 2][r] = f2tf(pa[i].z);
            As[p][a_ko + 3][r] = f2tf(pa[i].w);
        }
        #pragma unroll
        for (int i = 0; i < 2; i++) {
            int idx = t + i * 256;
            int kr  = idx >> 5;
            int c4  = (idx & 31) * 4;
            uint4 u;
            u.x = f2tf(pb[i].x); u.y = f2tf(pb[i].y); u.z = f2tf(pb[i].z); u.w = f2tf(pb[i].w);
            *(uint4*)&Bs[p][kr][c4] = u;
        }
        __syncthreads();

        if (kc + 1 < 16) {
            const int kbase = (kc + 1) * 16;
            #pragma unroll
            for (int i = 0; i < 2; i++) {
                int grow = bm + a_r + i * 64;
                pa[i] = (grow < M) ? *(const float4*)(A + (size_t)grow * EMBD + kbase + a_ko)
                                   : make_float4(0.f, 0.f, 0.f, 0.f);
            }
            #pragma unroll
            for (int i = 0; i < 2; i++) {
                int idx = t + i * 256;
                int kr  = idx >> 5;
                int c4  = (idx & 31) * 4;
                pb[i] = *(const float4*)(B + (size_t)(kbase + kr) * EMBD + bn + c4);
            }
        }

        #pragma unroll
        for (int k0 = 0; k0 < 16; k0 += 8) {
            uint32_t af[2][4], bf[8][2];
            const int kr0 = k0 + tig, kr1 = k0 + tig + 4;
            #pragma unroll
            for (int mt = 0; mt < 2; mt++) {
                int m0 = wr * 32 + mt * 16 + gid;
                af[mt][0] = As[p][kr0][m0];
                af[mt][1] = As[p][kr0][m0 + 8];
                af[mt][2] = As[p][kr1][m0];
                af[mt][3] = As[p][kr1][m0 + 8];
            }
            #pragma unroll
            for (int nt = 0; nt < 8; nt++) {
                int n0 = wc * 64 + nt * 8 + gid;
                bf[nt][0] = Bs[p][kr0][n0];
                bf[nt][1] = Bs[p][kr1][n0];
            }
            #pragma unroll
            for (int mt = 0; mt < 2; mt++)
                #pragma unroll
                for (int nt = 0; nt < 8; nt++) {
                    asm volatile(
                        "mma.sync.aligned.m16n8k8.row.col.f32.tf32.tf32.f32 "
                        "{%0,%1,%2,%3}, {%4,%5,%6,%7}, {%8,%9}, {%0,%1,%2,%3};\n"
                        : "+f"(acc[mt][nt][0]), "+f"(acc[mt][nt][1]),
                          "+f"(acc[mt][nt][2]), "+f"(acc[mt][nt][3])
                        : "r"(af[mt][0]), "r"(af[mt][1]), "r"(af[mt][2]), "r"(af[mt][3]),
                          "r"(bf[nt][0]), "r"(bf[nt][1]));
                }
        }
    }

    // store C
    #pragma unroll
    for (int mt = 0; mt < 2; mt++) {
        int row0 = bm + wr * 32 + mt * 16 + gid;
        #pragma unroll
        for (int nt = 0; nt < 8; nt++) {
            int col = bn + wc * 64 + nt * 8 + tig * 2;
            if (row0 < M)
                *(float2*)(C + (size_t)row0 * EMBD + col) = make_float2(acc[mt][nt][0], acc[mt][nt][1]);
            if (row0 + 8 < M)
                *(float2*)(C + (size_t)(row0 + 8) * EMBD + col) = make_float2(acc[mt][nt][2], acc[mt][nt][3]);
        }
    }

    // fused al epilogue
    float as_[16], ad_[16];
    #pragma unroll
    for (int nt = 0; nt < 8; nt++)
        #pragma unroll
        for (int c = 0; c < 2; c++) {
            int col = bn + wc * 64 + nt * 8 + tig * 2 + c;
            as_[nt * 2 + c] = __ldg(&asrc[col]);
            ad_[nt * 2 + c] = __ldg(&adst[col]);
        }

    #pragma unroll
    for (int mt = 0; mt < 2; mt++) {
        #pragma unroll
        for (int rs = 0; rs < 2; rs++) {
            float ps0 = 0.f, ps1 = 0.f, pd0 = 0.f, pd1 = 0.f;
            #pragma unroll
            for (int nt = 0; nt < 8; nt++)
                #pragma unroll
                for (int c = 0; c < 2; c++) {
                    float v = acc[mt][nt][rs * 2 + c];
                    float a = as_[nt * 2 + c], dd = ad_[nt * 2 + c];
                    if (nt < 4) { ps0 += v * a; pd0 += v * dd; }
                    else        { ps1 += v * a; pd1 += v * dd; }
                }
            if (H == 1) { ps0 += ps1; pd0 += pd1; }
            #pragma unroll
            for (int o = 1; o < 4; o <<= 1) {
                ps0 += __shfl_xor_sync(0xffffffffu, ps0, o);
                pd0 += __shfl_xor_sync(0xffffffffu, pd0, o);
                if (H == 8) {
                    ps1 += __shfl_xor_sync(0xffffffffu, ps1, o);
                    pd1 += __shfl_xor_sync(0xffffffffu, pd1, o);
                }
            }
            if (tig == 0) {
                int row = bm + wr * 32 + mt * 16 + gid + rs * 8;
                if (row < M) {
                    if (H == 8) {
                        int head0 = (bn >> 5) + wc * 2;
                        atomicAdd(&ALS[row * 8 + head0], ps0);
                        atomicAdd(&ALS[row * 8 + head0 + 1], ps1);
                        atomicAdd(&ALD[row * 8 + head0], pd0);
                        atomicAdd(&ALD[row * 8 + head0 + 1], pd1);
                    } else {
                        atomicAdd(&ALS[row], ps0);
                        atomicAdd(&ALD[row], pd0);
                    }
                }
            }
        }
    }
}

// ---------------- FUSED alpha + aggregation: 4 nodes/block, 64-thread groups ----------------
// 2 barriers per chunk: staging reads g_srcs directly and co-writes s_src.
template <int H, bool INTERNAL_DST>
__global__ void __launch_bounds__(256) agg_kernel(const float* __restrict__ bias,
                                                  float* __restrict__ outext) {
    const int t  = threadIdx.x;
    const int g  = t >> 6;
    const int t4 = t & 63;
    const int c0 = t4 * 4;
    const int hh = (H == 8) ? (c0 >> 5) : 0;
    const int d  = blockIdx.x * 4 + g;   // NN % 4 == 0

    const float* ALS = (H == 8) ? g_als : g_als2;
    const float* ALD = (H == 8) ? g_ald : g_ald2;

    __shared__ int   s_src[4][64];
    __shared__ float s_alpha[4][64 * H];

    const int begin = g_rowptr[d], end = g_rowptr[d + 1];
    const float aldv = ALD[d * H + ((H == 8) ? (t4 & 7) : 0)];

    float4 acc = make_float4(0.f, 0.f, 0.f, 0.f);
    float z = 0.f;

    for (int c = begin; c < end; c += 64) {
        int len = min(64, end - c);
        gbar(1 + g);                     // protect prior chunk's s_src/s_alpha reads
        if (H == 8) {
            for (int idx = t4; idx < len * 8; idx += 64) {
                int j = idx >> 3, h = idx & 7;       // h == t4&7 (stride 64)
                int s = __ldg(&g_srcs[c + j]);
                if (h == 0) s_src[g][j] = s;
                s_alpha[g][idx] = __expf(lrelu(__ldg(&ALS[s * 8 + h]) + aldv));
            }
        } else {
            for (int idx = t4; idx < len; idx += 64) {
                int s = __ldg(&g_srcs[c + idx]);
                s_src[g][idx] = s;
                s_alpha[g][idx] = __expf(lrelu(__ldg(&ALS[s]) + aldv));
            }
        }
        gbar(1 + g);
        for (int j = 0; j < len; j++) {
            float a = s_alpha[g][j * H + hh];
            z += a;
            const float4 hv = *(const float4*)(g_h + (size_t)s_src[g][j] * EMBD + c0);
            acc.x += a * hv.x; acc.y += a * hv.y; acc.z += a * hv.z; acc.w += a * hv.w;
        }
    }

    const float inv = 1.f / (z + 1e-16f);
    const float4 bv = *(const float4*)(bias + c0);
    float4 r = make_float4(acc.x * inv + bv.x, acc.y * inv + bv.y,
                           acc.z * inv + bv.z, acc.w * inv + bv.w);
    float* dst = INTERNAL_DST ? (g_o1 + (size_t)d * EMBD + c0)
                              : (outext + (size_t)d * EMBD + c0);
    *(float4*)dst = r;
}

// ---------------- launch ----------------
extern "C" void kernel_launch(void* const* d_in, const int* in_sizes, int n_in,
                              void* d_out, int out_size) {
    const float* x   = (const float*)d_in[0];
    const void*  ei  = d_in[1];
    const float* W1  = (const float*)d_in[2];
    const float* as1 = (const float*)d_in[3];
    const float* ad1 = (const float*)d_in[4];
    const float* b1  = (const float*)d_in[5];
    const float* W2  = (const float*)d_in[6];
    const float* as2 = (const float*)d_in[7];
    const float* ad2 = (const float*)d_in[8];
    const float* b2  = (const float*)d_in[9];
    float* out = (float*)d_out;

    init_kernel<<<(NN * 8 + 255) / 256, 256>>>(ei);
    deg_kernel<<<(NE / 4 + 255) / 256, 256>>>(ei);
    scan1_kernel<<<NBLK, 256>>>();
    scan_apply_kernel<<<NBLK, 256>>>();
    scatter_kernel<<<(NE / 4 + 255) / 256, 256>>>(ei);

    dim3 gg((NN + 127) / 128, 2);
    const int AGB = NN / 4;

    // layer 1 (H=8, F=32)
    gemm_tc_kernel<8, false><<<gg, 256>>>(x, W1, as1, ad1, NN);
    agg_kernel<8, true><<<AGB, 256>>>(b1, nullptr);

    // layer 2 (H=1, F=256)
    gemm_tc_kernel<1, true><<<gg, 256>>>(nullptr, W2, as2, ad2, NN);
    agg_kernel<1, false><<<AGB, 256>>>(b2, out);
}

// round 17
// speedup vs baseline: 1.0833x; 1.0479x over previous
#include <cuda_runtime.h>
#include <cstdint>

#define NN   50000
#define EMBD 256
#define NE   800000
#define ETOT (NE + NN)
#define NBLK 196                      // ceil(NN/256)

// ---------------- static device scratch ----------------
__device__ float g_h[(size_t)NN * EMBD];
__device__ float g_o1[(size_t)NN * EMBD];
__device__ float g_als[NN * 8];       // layer-1 (H=8) logit pieces
__device__ float g_ald[NN * 8];
__device__ float g_als2[NN];          // layer-2 (H=1)
__device__ float g_ald2[NN];
__device__ int   g_rowptr[NN + 1];
__device__ int   g_cnt[NN];
__device__ int   g_srcs[ETOT];
__device__ int   g_tmp[NN];
__device__ int   g_bsum[NBLK];
__device__ int   g_is64;

__device__ __forceinline__ float lrelu(float x) { return x > 0.f ? x : 0.2f * x; }

__device__ __forceinline__ uint32_t f2tf(float f) {
    uint32_t u;
    asm("cvt.rna.tf32.f32 %0, %1;" : "=r"(u) : "f"(f));
    return u;
}

__device__ __forceinline__ void gbar(int id) {
    asm volatile("bar.sync %0, 64;" :: "r"(id) : "memory");
}

// ---------------- stream B head: zero counters + dtype probe ----------------
__global__ void zero_cnt_detect_kernel(const void* ei) {
    const int i = blockIdx.x * blockDim.x + threadIdx.x;
    if (i < NN) g_cnt[i] = 0;
    if (i == 0) {
        const long long* p = (const long long*)ei;
        bool ok = true;
        #pragma unroll
        for (int k = 0; k < 8; k++) {
            long long v = p[k];
            if (v < 0 || v >= NN) ok = false;
        }
        g_is64 = ok ? 1 : 0;
    }
}

// ---------------- main stream head: zero logit accumulators ----------------
__global__ void zero_al_kernel() {
    const int i = blockIdx.x * blockDim.x + threadIdx.x;
    const int stride = gridDim.x * blockDim.x;
    if (i < NN) { g_als2[i] = 0.f; g_ald2[i] = 0.f; }
    for (int j = i; j < NN * 8; j += stride) { g_als[j] = 0.f; g_ald[j] = 0.f; }
}

// ---------------- CSR build (4 edges / thread) ----------------
__global__ void deg_kernel(const void* __restrict__ ei) {
    int e4 = blockIdx.x * blockDim.x + threadIdx.x;
    if (e4 >= NE / 4) return;
    if (!g_is64) {
        int4 d = ((const int4*)((const int*)ei + NE))[e4];
        atomicAdd(&g_cnt[d.x], 1);
        atomicAdd(&g_cnt[d.y], 1);
        atomicAdd(&g_cnt[d.z], 1);
        atomicAdd(&g_cnt[d.w], 1);
    } else {
        const long long* p = (const long long*)ei + NE;
        #pragma unroll
        for (int k = 0; k < 4; k++) atomicAdd(&g_cnt[(int)p[e4 * 4 + k]], 1);
    }
}

__global__ void __launch_bounds__(256) scan1_kernel() {
    __shared__ int wsum[8];
    const int t = threadIdx.x, b = blockIdx.x;
    const int i = b * 256 + t;
    int v = (i < NN) ? g_cnt[i] + 1 : 0;
    int x = v;
    #pragma unroll
    for (int o = 1; o < 32; o <<= 1) {
        int y = __shfl_up_sync(0xffffffffu, x, o);
        if ((t & 31) >= o) x += y;
    }
    if ((t & 31) == 31) wsum[t >> 5] = x;
    __syncthreads();
    if (t < 8) {
        int w = wsum[t];
        #pragma unroll
        for (int o = 1; o < 8; o <<= 1) {
            int y = __shfl_up_sync(0xffu, w, o);
            if (t >= o) w += y;
        }
        wsum[t] = w;
    }
    __syncthreads();
    int incl = x + ((t >= 32) ? wsum[(t >> 5) - 1] : 0);
    if (i < NN) g_tmp[i] = incl;
    if (t == 255) g_bsum[b] = incl;
}

// merged scan2+scan3
__global__ void __launch_bounds__(256) scan_apply_kernel() {
    __shared__ int red[8];
    __shared__ int s_off;
    const int t = threadIdx.x, b = blockIdx.x;
    int v = (t < b) ? g_bsum[t] : 0;
    #pragma unroll
    for (int o = 16; o; o >>= 1) v += __shfl_xor_sync(0xffffffffu, v, o);
    if ((t & 31) == 0) red[t >> 5] = v;
    __syncthreads();
    if (t == 0) {
        int s = 0;
        #pragma unroll
        for (int ww = 0; ww < 8; ww++) s += red[ww];
        s_off = s;
        if (b == 0) g_rowptr[0] = 0;
    }
    __syncthreads();
    const int i = b * 256 + t;
    if (i < NN) {
        int rp1 = g_tmp[i] + s_off;
        g_rowptr[i + 1] = rp1;
        g_cnt[i] = 0;
        g_srcs[rp1 - 1] = i;
    }
}

__global__ void scatter_kernel(const void* __restrict__ ei) {
    int e4 = blockIdx.x * blockDim.x + threadIdx.x;
    if (e4 >= NE / 4) return;
    int s[4], d[4];
    if (!g_is64) {
        int4 sv = ((const int4*)ei)[e4];
        int4 dv = ((const int4*)((const int*)ei + NE))[e4];
        s[0] = sv.x; s[1] = sv.y; s[2] = sv.z; s[3] = sv.w;
        d[0] = dv.x; d[1] = dv.y; d[2] = dv.z; d[3] = dv.w;
    } else {
        const long long* ps = (const long long*)ei;
        const long long* pd = ps + NE;
        #pragma unroll
        for (int k = 0; k < 4; k++) { s[k] = (int)ps[e4 * 4 + k]; d[k] = (int)pd[e4 * 4 + k]; }
    }
    #pragma unroll
    for (int k = 0; k < 4; k++) {
        int pos = g_rowptr[d[k]] + atomicAdd(&g_cnt[d[k]], 1);
        g_srcs[pos] = s[k];
    }
}

// ---------------- tf32 GEMM, 2-stage double-buffered, 2 CTAs/SM, fused al epilogue ----------
template <int H, bool INTERNAL_SRC>
__global__ void __launch_bounds__(256, 2) gemm_tc_kernel(const float* __restrict__ Aext,
                                                         const float* __restrict__ B,
                                                         const float* __restrict__ asrc,
                                                         const float* __restrict__ adst, int M) {
    const float* A = INTERNAL_SRC ? g_o1 : Aext;
    float* C = g_h;
    float* ALS = (H == 8) ? g_als : g_als2;
    float* ALD = (H == 8) ? g_ald : g_ald2;

    __shared__ uint32_t As[2][16][129];
    __shared__ uint32_t Bs[2][16][132];

    const int t    = threadIdx.x;
    const int lane = t & 31;
    const int w    = t >> 5;
    const int wr   = w & 3;
    const int wc   = w >> 2;
    const int tig  = lane & 3;
    const int gid  = lane >> 2;
    const int bm   = blockIdx.x * 128;
    const int bn   = blockIdx.y * 128;

    float acc[2][8][4];
    #pragma unroll
    for (int mt = 0; mt < 2; mt++)
        #pragma unroll
        for (int nt = 0; nt < 8; nt++)
            #pragma unroll
            for (int c = 0; c < 4; c++) acc[mt][nt][c] = 0.f;

    const int a_r  = t >> 2;           // 0..63
    const int a_ko = (t & 3) * 4;      // 0,4,8,12

    float4 pa[2], pb[2];

    // prefetch chunk 0
    #pragma unroll
    for (int i = 0; i < 2; i++) {
        int grow = bm + a_r + i * 64;
        pa[i] = (grow < M) ? *(const float4*)(A + (size_t)grow * EMBD + a_ko)
                           : make_float4(0.f, 0.f, 0.f, 0.f);
    }
    #pragma unroll
    for (int i = 0; i < 2; i++) {
        int idx = t + i * 256;
        int kr  = idx >> 5;            // 0..15
        int c4  = (idx & 31) * 4;
        pb[i] = *(const float4*)(B + (size_t)kr * EMBD + bn + c4);
    }

    #pragma unroll 1
    for (int kc = 0; kc < 16; kc++) {
        const int p = kc & 1;
        #pragma unroll
        for (int i = 0; i < 2; i++) {
            int r = a_r + i * 64;
            As[p][a_ko + 0][r] = f2tf(pa[i].x);
            As[p][a_ko + 1][r] = f2tf(pa[i].y);
            As[p][a_ko + 2][r] = f2tf(pa[i].z);
            As[p][a_ko + 3][r] = f2tf(pa[i].w);
        }
        #pragma unroll
        for (int i = 0; i < 2; i++) {
            int idx = t + i * 256;
            int kr  = idx >> 5;
            int c4  = (idx & 31) * 4;
            uint4 u;
            u.x = f2tf(pb[i].x); u.y = f2tf(pb[i].y); u.z = f2tf(pb[i].z); u.w = f2tf(pb[i].w);
            *(uint4*)&Bs[p][kr][c4] = u;
        }
        __syncthreads();

        if (kc + 1 < 16) {
            const int kbase = (kc + 1) * 16;
            #pragma unroll
            for (int i = 0; i < 2; i++) {
                int grow = bm + a_r + i * 64;
                pa[i] = (grow < M) ? *(const float4*)(A + (size_t)grow * EMBD + kbase + a_ko)
                                   : make_float4(0.f, 0.f, 0.f, 0.f);
            }
            #pragma unroll
            for (int i = 0; i < 2; i++) {
                int idx = t + i * 256;
                int kr  = idx >> 5;
                int c4  = (idx & 31) * 4;
                pb[i] = *(const float4*)(B + (size_t)(kbase + kr) * EMBD + bn + c4);
            }
        }

        #pragma unroll
        for (int k0 = 0; k0 < 16; k0 += 8) {
            uint32_t af[2][4], bf[8][2];
            const int kr0 = k0 + tig, kr1 = k0 + tig + 4;
            #pragma unroll
            for (int mt = 0; mt < 2; mt++) {
                int m0 = wr * 32 + mt * 16 + gid;
                af[mt][0] = As[p][kr0][m0];
                af[mt][1] = As[p][kr0][m0 + 8];
                af[mt][2] = As[p][kr1][m0];
                af[mt][3] = As[p][kr1][m0 + 8];
            }
            #pragma unroll
            for (int nt = 0; nt < 8; nt++) {
                int n0 = wc * 64 + nt * 8 + gid;
                bf[nt][0] = Bs[p][kr0][n0];
                bf[nt][1] = Bs[p][kr1][n0];
            }
            #pragma unroll
            for (int mt = 0; mt < 2; mt++)
                #pragma unroll
                for (int nt = 0; nt < 8; nt++) {
                    asm volatile(
                        "mma.sync.aligned.m16n8k8.row.col.f32.tf32.tf32.f32 "
                        "{%0,%1,%2,%3}, {%4,%5,%6,%7}, {%8,%9}, {%0,%1,%2,%3};\n"
                        : "+f"(acc[mt][nt][0]), "+f"(acc[mt][nt][1]),
                          "+f"(acc[mt][nt][2]), "+f"(acc[mt][nt][3])
                        : "r"(af[mt][0]), "r"(af[mt][1]), "r"(af[mt][2]), "r"(af[mt][3]),
                          "r"(bf[nt][0]), "r"(bf[nt][1]));
                }
        }
    }

    // store C
    #pragma unroll
    for (int mt = 0; mt < 2; mt++) {
        int row0 = bm + wr * 32 + mt * 16 + gid;
        #pragma unroll
        for (int nt = 0; nt < 8; nt++) {
            int col = bn + wc * 64 + nt * 8 + tig * 2;
            if (row0 < M)
                *(float2*)(C + (size_t)row0 * EMBD + col) = make_float2(acc[mt][nt][0], acc[mt][nt][1]);
            if (row0 + 8 < M)
                *(float2*)(C + (size_t)(row0 + 8) * EMBD + col) = make_float2(acc[mt][nt][2], acc[mt][nt][3]);
        }
    }

    // fused al epilogue
    float as_[16], ad_[16];
    #pragma unroll
    for (int nt = 0; nt < 8; nt++)
        #pragma unroll
        for (int c = 0; c < 2; c++) {
            int col = bn + wc * 64 + nt * 8 + tig * 2 + c;
            as_[nt * 2 + c] = __ldg(&asrc[col]);
            ad_[nt * 2 + c] = __ldg(&adst[col]);
        }

    #pragma unroll
    for (int mt = 0; mt < 2; mt++) {
        #pragma unroll
        for (int rs = 0; rs < 2; rs++) {
            float ps0 = 0.f, ps1 = 0.f, pd0 = 0.f, pd1 = 0.f;
            #pragma unroll
            for (int nt = 0; nt < 8; nt++)
                #pragma unroll
                for (int c = 0; c < 2; c++) {
                    float v = acc[mt][nt][rs * 2 + c];
                    float a = as_[nt * 2 + c], dd = ad_[nt * 2 + c];
                    if (nt < 4) { ps0 += v * a; pd0 += v * dd; }
                    else        { ps1 += v * a; pd1 += v * dd; }
                }
            if (H == 1) { ps0 += ps1; pd0 += pd1; }
            #pragma unroll
            for (int o = 1; o < 4; o <<= 1) {
                ps0 += __shfl_xor_sync(0xffffffffu, ps0, o);
                pd0 += __shfl_xor_sync(0xffffffffu, pd0, o);
                if (H == 8) {
                    ps1 += __shfl_xor_sync(0xffffffffu, ps1, o);
                    pd1 += __shfl_xor_sync(0xffffffffu, pd1, o);
                }
            }
            if (tig == 0) {
                int row = bm + wr * 32 + mt * 16 + gid + rs * 8;
                if (row < M) {
                    if (H == 8) {
                        int head0 = (bn >> 5) + wc * 2;
                        atomicAdd(&ALS[row * 8 + head0], ps0);
                        atomicAdd(&ALS[row * 8 + head0 + 1], ps1);
                        atomicAdd(&ALD[row * 8 + head0], pd0);
                        atomicAdd(&ALD[row * 8 + head0 + 1], pd1);
                    } else {
                        atomicAdd(&ALS[row], ps0);
                        atomicAdd(&ALD[row], pd0);
                    }
                }
            }
        }
    }
}

// ---------------- FUSED alpha + aggregation: 4 nodes/block, 64-thread groups ----------------
template <int H, bool INTERNAL_DST>
__global__ void __launch_bounds__(256) agg_kernel(const float* __restrict__ bias,
                                                  float* __restrict__ outext) {
    const int t  = threadIdx.x;
    const int g  = t >> 6;
    const int t4 = t & 63;
    const int c0 = t4 * 4;
    const int hh = (H == 8) ? (c0 >> 5) : 0;
    const int d  = blockIdx.x * 4 + g;   // NN % 4 == 0

    const float* ALS = (H == 8) ? g_als : g_als2;
    const float* ALD = (H == 8) ? g_ald : g_ald2;

    __shared__ int   s_src[4][64];
    __shared__ float s_alpha[4][64 * H];

    const int begin = g_rowptr[d], end = g_rowptr[d + 1];
    const float aldv = ALD[d * H + ((H == 8) ? (t4 & 7) : 0)];

    float4 acc = make_float4(0.f, 0.f, 0.f, 0.f);
    float z = 0.f;

    for (int c = begin; c < end; c += 64) {
        int len = min(64, end - c);
        gbar(1 + g);                     // protect prior chunk's s_src/s_alpha reads
        if (H == 8) {
            for (int idx = t4; idx < len * 8; idx += 64) {
                int j = idx >> 3, h = idx & 7;       // h == t4&7 (stride 64)
                int s = __ldg(&g_srcs[c + j]);
                if (h == 0) s_src[g][j] = s;
                s_alpha[g][idx] = __expf(lrelu(__ldg(&ALS[s * 8 + h]) + aldv));
            }
        } else {
            for (int idx = t4; idx < len; idx += 64) {
                int s = __ldg(&g_srcs[c + idx]);
                s_src[g][idx] = s;
                s_alpha[g][idx] = __expf(lrelu(__ldg(&ALS[s]) + aldv));
            }
        }
        gbar(1 + g);
        for (int j = 0; j < len; j++) {
            float a = s_alpha[g][j * H + hh];
            z += a;
            const float4 hv = *(const float4*)(g_h + (size_t)s_src[g][j] * EMBD + c0);
            acc.x += a * hv.x; acc.y += a * hv.y; acc.z += a * hv.z; acc.w += a * hv.w;
        }
    }

    const float inv = 1.f / (z + 1e-16f);
    const float4 bv = *(const float4*)(bias + c0);
    float4 r = make_float4(acc.x * inv + bv.x, acc.y * inv + bv.y,
                           acc.z * inv + bv.z, acc.w * inv + bv.w);
    float* dst = INTERNAL_DST ? (g_o1 + (size_t)d * EMBD + c0)
                              : (outext + (size_t)d * EMBD + c0);
    *(float4*)dst = r;
}

// ---------------- launch: CSR build forked onto a second stream ----------------
extern "C" void kernel_launch(void* const* d_in, const int* in_sizes, int n_in,
                              void* d_out, int out_size) {
    const float* x   = (const float*)d_in[0];
    const void*  ei  = d_in[1];
    const float* W1  = (const float*)d_in[2];
    const float* as1 = (const float*)d_in[3];
    const float* ad1 = (const float*)d_in[4];
    const float* b1  = (const float*)d_in[5];
    const float* W2  = (const float*)d_in[6];
    const float* as2 = (const float*)d_in[7];
    const float* ad2 = (const float*)d_in[8];
    const float* b2  = (const float*)d_in[9];
    float* out = (float*)d_out;

    // fork-join plumbing (created per call; NOT destroyed — destroying a
    // capture-joined stream mid-capture would invalidate the graph, and
    // kernel_launch only runs a handful of times, all host-side objects).
    cudaStream_t sb;
    cudaEvent_t e1, e2;
    cudaStreamCreateWithFlags(&sb, cudaStreamNonBlocking);
    cudaEventCreateWithFlags(&e1, cudaEventDisableTiming);
    cudaEventCreateWithFlags(&e2, cudaEventDisableTiming);

    // fork: streamB branches off the (capturing) default stream
    cudaEventRecord(e1, 0);
    cudaStreamWaitEvent(sb, e1, 0);

    // stream B: CSR build (independent of GEMM-1)
    zero_cnt_detect_kernel<<<NBLK, 256, 0, sb>>>(ei);
    deg_kernel<<<(NE / 4 + 255) / 256, 256, 0, sb>>>(ei);
    scan1_kernel<<<NBLK, 256, 0, sb>>>();
    scan_apply_kernel<<<NBLK, 256, 0, sb>>>();
    scatter_kernel<<<(NE / 4 + 255) / 256, 256, 0, sb>>>(ei);
    cudaEventRecord(e2, sb);

    dim3 gg((NN + 127) / 128, 2);
    const int AGB = NN / 4;

    // main stream: logit-accumulator zero + GEMM-1 (overlaps CSR build)
    zero_al_kernel<<<(NN * 8 + 255) / 256, 256>>>();
    gemm_tc_kernel<8, false><<<gg, 256>>>(x, W1, as1, ad1, NN);

    // join: agg-1 needs both the CSR and GEMM-1
    cudaStreamWaitEvent(0, e2, 0);
    agg_kernel<8, true><<<AGB, 256>>>(b1, nullptr);

    // layer 2 (H=1, F=256) — strictly serial
    gemm_tc_kernel<1, true><<<gg, 256>>>(nullptr, W2, as2, ad2, NN);
    agg_kernel<1, false><<<AGB, 256>>>(b2, out);
}